// round 11
// baseline (speedup 1.0000x reference)
#include <cuda_runtime.h>

#define NB 4
#define NK 128
#define NG 128

// ---- output layout (float32, tuple flattened & concatenated) ----
#define OFF_ROIS    0
#define OFF_OBJ     2048
#define OFF_DELTAS  526336
#define OFF_RANKS   528384
#define OFF_SPATIAL 528896

// packed meta per SOURCE proposal:
//   .x = (dest << 16) | (by1 & 0xFFFF)   (by1 sign-extended on read)
//   .y = bx1   .z = by2   .w = bx2
__device__ int4 g_meta [NB * NK];
__device__ int  g_ready[NB * NK];    // zero-init; each consumer resets its own

// grid = 512, block = 256 (verified config).
__global__ void __launch_bounds__(256) fused_kernel(
    const float* __restrict__ proposals,
    const float* __restrict__ obj_feat,
    const float* __restrict__ gt_boxes,
    const int*   __restrict__ gt_ranks,
    float*       __restrict__ out)
{
    const int bo = blockIdx.x;           // source index b*128 + p_src
    const int b  = bo >> 7;
    const int t  = threadIdx.x;

    // ---- payload load FIRST: independent of setup, overlaps everything ----
    const float4 payload = ((const float4*)obj_feat)[(size_t)bo * 256 + t];

    // ---- blocks with p_src == 0 run setup for their image ----
    // (blockIdx-uniform condition: every __syncthreads() below is reached by
    //  all 256 threads of the block)
    if ((bo & 127) == 0) {
        __shared__ float4 s_prop[NK];
        __shared__ float4 s_gt[NG];
        __shared__ float  s_bi[2][NK];
        __shared__ float  s_bu[2][NK];
        __shared__ int    s_bj[2][NK];
        __shared__ unsigned s_mask[4];

        if (t < NK) s_prop[t]    = ((const float4*)proposals)[b * NK + t];
        else        s_gt[t - NK] = ((const float4*)gt_boxes)[b * NG + (t - NK)];
        __syncthreads();

        // division-free segmented argmax with DUAL accumulators:
        // seg = t>>7 owns GTs [64*seg, 64*seg+64); stream A = first 32,
        // stream B = last 32, independent dep chains, merged in index order.
        {
            const int seg = t >> 7;
            const int p   = t & 127;
            const float4 pr = s_prop[p];
            const float ap = (pr.z - pr.x) * (pr.w - pr.y);
            const int j0 = seg * 64;
            float biA = -1.0f, buA = 1.0f; int bjA = j0;
            float biB = -1.0f, buB = 1.0f; int bjB = j0 + 32;
            #pragma unroll 8
            for (int j = 0; j < 32; j++) {
                {   // stream A: GT j0 + j
                    const float4 gb = s_gt[j0 + j];
                    const float dy = fminf(pr.z, gb.z) - fmaxf(pr.x, gb.x);
                    const float dx = fminf(pr.w, gb.w) - fmaxf(pr.y, gb.y);
                    const float inter = fmaxf(dx, 0.0f) * fmaxf(dy, 0.0f);
                    const float u = ap + (gb.z - gb.x) * (gb.w - gb.y) - inter;
                    if (inter * buA > biA * u) { biA = inter; buA = u; bjA = j0 + j; }
                }
                {   // stream B: GT j0 + 32 + j
                    const float4 gb = s_gt[j0 + 32 + j];
                    const float dy = fminf(pr.z, gb.z) - fmaxf(pr.x, gb.x);
                    const float dx = fminf(pr.w, gb.w) - fmaxf(pr.y, gb.y);
                    const float inter = fmaxf(dx, 0.0f) * fmaxf(dy, 0.0f);
                    const float u = ap + (gb.z - gb.x) * (gb.w - gb.y) - inter;
                    if (inter * buB > biB * u) { biB = inter; buB = u; bjB = j0 + 32 + j; }
                }
            }
            // merge B into A (strict > keeps lower-index stream A on tie)
            if (biB * buA > biA * buB) { biA = biB; buA = buB; bjA = bjB; }
            s_bi[seg][p] = biA;
            s_bu[seg][p] = buA;
            s_bj[seg][p] = bjA;
        }
        __syncthreads();

        // merge segments + exact winner IoU + ballot (warps 0-3 fully active)
        int pos = 0, bj = 0;
        if (t < NK) {
            float bi = s_bi[0][t], bu = s_bu[0][t];
            bj = s_bj[0][t];
            const float bi1 = s_bi[1][t], bu1 = s_bu[1][t];
            if (bi1 * bu > bi * bu1) { bi = bi1; bu = bu1; bj = s_bj[1][t]; }

            const float4 pr = s_prop[t];
            const float4 gb = s_gt[bj];
            // exact IoU for the winner (bit-matches reference threshold test)
            const float ap = (pr.z - pr.x) * (pr.w - pr.y);
            const float iy1 = fmaxf(pr.x, gb.x);
            const float ix1 = fmaxf(pr.y, gb.y);
            const float iy2 = fminf(pr.z, gb.z);
            const float ix2 = fminf(pr.w, gb.w);
            const float inter = fmaxf(ix2 - ix1, 0.0f) * fmaxf(iy2 - iy1, 0.0f);
            const float ag = (gb.z - gb.x) * (gb.w - gb.y);
            const float iou = inter / (ap + ag - inter);
            pos = (iou >= 0.5f) ? 1 : 0;

            const unsigned m = __ballot_sync(0xFFFFFFFFu, pos);
            if ((t & 31) == 0) s_mask[t >> 5] = m;
        }
        __syncthreads();   // block-level barrier

        if (t < NK) {
            const unsigned m0 = s_mask[0], m1 = s_mask[1], m2 = s_mask[2], m3 = s_mask[3];
            const int npos = __popc(m0) + __popc(m1) + __popc(m2) + __popc(m3);
            const int w = t >> 5, l = t & 31;
            const unsigned below = (l == 0) ? 0u : (s_mask[w] & ((1u << l) - 1u));
            int rank_pos = __popc(below);
            if (w > 0) rank_pos += __popc(m0);
            if (w > 1) rank_pos += __popc(m1);
            if (w > 2) rank_pos += __popc(m2);
            const int dest = pos ? rank_pos : (npos + (t - rank_pos));

            const int sbo = (b << 7) + t;
            const int dbo = (b << 7) + dest;

            const float4 pr = s_prop[t];
            const float4 gb = s_gt[bj];
            float gy1 = gb.x, gx1 = gb.y, gy2 = gb.z, gx2 = gb.w;
            if (!pos) { gy1 = gx1 = gy2 = gx2 = 0.0f; }   // roi_gt = 0 for negatives

            // ---- publish packed consumer meta, then release ----
            {
                // integer spatial box (window transform + denorm + round-half-even)
                const float win0 = 128.0f / 1023.0f;
                const float win2 = 895.0f / 1023.0f;
                const float wsc  = win2 - win0;
                int by1 = (int)rintf(((gy1 - win0) / wsc) * 479.0f);
                int bx1 = (int)rintf(gx1 * 639.0f);
                int by2 = (int)rintf(((gy2 - win0) / wsc) * 479.0f + 1.0f);
                int bx2 = (int)rintf(gx2 * 639.0f + 1.0f);
                if (!((by2 - by1) * (bx2 - bx1) > 0)) { by1 = bx1 = by2 = bx2 = 0; }
                g_meta[sbo] = make_int4((dest << 16) | (by1 & 0xFFFF), bx1, by2, bx2);
            }
            // st.release orders this thread's g_meta store before the flag
            asm volatile("st.release.gpu.global.b32 [%0], %1;"
                         :: "l"(&g_ready[sbo]), "r"(1) : "memory");

            // ---- epilogue (not consumer-critical): rois / deltas / ranks ----
            ((float4*)(out + OFF_ROIS))[dbo] = pr;
            float4 dl = make_float4(0.f, 0.f, 0.f, 0.f);
            float rk = 0.0f;
            if (pos) {
                const float h  = pr.z - pr.x, wd = pr.w - pr.y;
                const float cy = pr.x + 0.5f * h, cx = pr.y + 0.5f * wd;
                const float gh = gy2 - gy1, gw = gx2 - gx1;
                const float gcy = gy1 + 0.5f * gh, gcx = gx1 + 0.5f * gw;
                dl.x = ((gcy - cy) / h)  / 0.1f;
                dl.y = ((gcx - cx) / wd) / 0.1f;
                dl.z = logf(gh / h)  / 0.2f;
                dl.w = logf(gw / wd) / 0.2f;
                rk = (float)gt_ranks[b * NG + bj];
            }
            ((float4*)(out + OFF_DELTAS))[dbo] = dl;
            out[OFF_RANKS + dbo] = rk;
        }
    }

    // ---- handshake: one poller per flag; bounded tight spin, then backoff ----
    if (t == 0) {
        int v;
        asm volatile("ld.acquire.gpu.global.b32 %0, [%1];"
                     : "=r"(v) : "l"(&g_ready[bo]) : "memory");
        int spins = 0;
        while (v == 0) {
            if (++spins > 64) __nanosleep(40);
            asm volatile("ld.acquire.gpu.global.b32 %0, [%1];"
                         : "=r"(v) : "l"(&g_ready[bo]) : "memory");
        }
        g_ready[bo] = 0;   // self-reset (single reader, ordered after the read)
    }
    __syncthreads();       // block-level: publishes acquire to all threads

    // ---- scatter: single packed-meta load, then write payload + spatial ----
    const int4 mt  = g_meta[bo];
    const int dest = mt.x >> 16;
    const int by1  = (int)(short)(mt.x & 0xFFFF);
    const int dbo  = (b << 7) + dest;

    ((float4*)(out + OFF_OBJ))[(size_t)dbo * 256 + t] = payload;

    // analytic spatial: thread t writes float4 covering elements [4t, 4t+4)
    const int row  = t >> 3;
    const int col0 = (t & 7) * 4;
    float4 v = make_float4(0.f, 0.f, 0.f, 0.f);
    if (row >= 4 && row < 28) {
        const int r1 = 20 * (row - 4) + 9;
        const float fy = (float)((by1 < r1)     && (r1     < mt.z))
                       + (float)((by1 < r1 + 1) && (r1 + 1 < mt.z));
        const float sc = 0.25f * fy;
        float* vv = &v.x;
        #pragma unroll
        for (int k = 0; k < 4; k++) {
            const int c1 = 20 * (col0 + k) + 9;
            const float fx = (float)((mt.y < c1)     && (c1     < mt.w))
                           + (float)((mt.y < c1 + 1) && (c1 + 1 < mt.w));
            vv[k] = sc * fx;
        }
    }
    ((float4*)(out + OFF_SPATIAL))[(size_t)dbo * 256 + t] = v;
}

extern "C" void kernel_launch(void* const* d_in, const int* in_sizes, int n_in,
                              void* d_out, int out_size)
{
    const float* proposals = (const float*)d_in[0];
    const float* obj_feat  = (const float*)d_in[1];
    const float* gt_boxes  = (const float*)d_in[2];
    const int*   gt_ranks  = (const int*)  d_in[3];
    float* out = (float*)d_out;

    fused_kernel<<<NB * NK, 256>>>(proposals, obj_feat, gt_boxes, gt_ranks, out);
}

// round 12
// speedup vs baseline: 1.1744x; 1.1744x over previous
#include <cuda_runtime.h>

#define NB 4
#define NK 128
#define NG 128

// ---- output layout (float32, tuple flattened & concatenated) ----
#define OFF_ROIS    0
#define OFF_OBJ     2048
#define OFF_DELTAS  526336
#define OFF_RANKS   528384
#define OFF_SPATIAL 528896

// Per-image sync state, one 128B line each (zero-initialized; the 128th
// done-arriver of each image resets it for the next launch).
struct __align__(128) ImgSync {
    unsigned long long arrive[2];   // 128 arrival bits
    unsigned long long pos[2];      // 128 positive bits
    int done;
    int pad[23];
};
__device__ ImgSync g_sync[NB];

// grid = 512, block = 256. Block bo = b*128 + p handles SOURCE proposal p of
// image b end-to-end: own argmax (128 IoUs, 1/thread), publish pos+arrive bits,
// wait for the image's 128 arrivals, compute dest locally, scatter.
__global__ void __launch_bounds__(256) fused_kernel(
    const float* __restrict__ proposals,
    const float* __restrict__ obj_feat,
    const float* __restrict__ gt_boxes,
    const int*   __restrict__ gt_ranks,
    float*       __restrict__ out)
{
    const int bo = blockIdx.x;
    const int b  = bo >> 7;
    const int p  = bo & 127;
    const int t  = threadIdx.x;

    // ---- payload load first: overlaps everything ----
    const float4 payload = ((const float4*)obj_feat)[(size_t)bo * 256 + t];

    __shared__ float s_bi[4], s_bu[4];
    __shared__ int   s_bj[4];
    __shared__ int   s_dest;
    __shared__ int4  s_box;

    // ---- per-thread IoU: thread t (t<128) handles GT index t ----
    if (t < NG) {
        const float4 pr = ((const float4*)proposals)[bo];          // broadcast
        const float4 g  = ((const float4*)gt_boxes)[(b << 7) + t];
        const float ap = (pr.z - pr.x) * (pr.w - pr.y);
        const float dy = fminf(pr.z, g.z) - fmaxf(pr.x, g.x);
        const float dx = fminf(pr.w, g.w) - fmaxf(pr.y, g.y);
        float bi = fmaxf(dx, 0.0f) * fmaxf(dy, 0.0f);              // inter
        float bu = ap + (g.z - g.x) * (g.w - g.y) - bi;            // union
        int   bj = t;
        // warp argmax; shfl_down partner always has HIGHER gt index, so
        // strict > keeps the first (lowest-index) max — matches jnp.argmax.
        #pragma unroll
        for (int off = 16; off; off >>= 1) {
            const float oi = __shfl_down_sync(0xFFFFFFFFu, bi, off);
            const float ou = __shfl_down_sync(0xFFFFFFFFu, bu, off);
            const int   oj = __shfl_down_sync(0xFFFFFFFFu, bj, off);
            if (oi * bu > bi * ou) { bi = oi; bu = ou; bj = oj; }
        }
        if ((t & 31) == 0) { s_bi[t >> 5] = bi; s_bu[t >> 5] = bu; s_bj[t >> 5] = bj; }
    }
    __syncthreads();

    if (t == 0) {
        // merge 4 warp winners in ascending-index order
        float bi = s_bi[0], bu = s_bu[0];
        int   bj = s_bj[0];
        #pragma unroll
        for (int w = 1; w < 4; w++)
            if (s_bi[w] * bu > bi * s_bu[w]) { bi = s_bi[w]; bu = s_bu[w]; bj = s_bj[w]; }

        const float4 pr = ((const float4*)proposals)[bo];
        const float4 gb = ((const float4*)gt_boxes)[(b << 7) + bj];

        // exact IoU for the winner (bit-matches reference threshold test)
        const float ap = (pr.z - pr.x) * (pr.w - pr.y);
        const float iy1 = fmaxf(pr.x, gb.x);
        const float ix1 = fmaxf(pr.y, gb.y);
        const float iy2 = fminf(pr.z, gb.z);
        const float ix2 = fminf(pr.w, gb.w);
        const float inter = fmaxf(ix2 - ix1, 0.0f) * fmaxf(iy2 - iy1, 0.0f);
        const float ag = (gb.z - gb.x) * (gb.w - gb.y);
        const float iou = inter / (ap + ag - inter);
        const int pos = (iou >= 0.5f) ? 1 : 0;

        // ---- publish this proposal's bits (RED: no-return, ~1 cyc/op) ----
        ImgSync* S = &g_sync[b];
        const unsigned long long bit = 1ULL << (p & 63);
        const int w64 = p >> 6;
        if (pos)
            asm volatile("red.relaxed.gpu.global.or.b64 [%0], %1;"
                         :: "l"(&S->pos[w64]), "l"(bit) : "memory");
        asm volatile("red.release.gpu.global.or.b64 [%0], %1;"
                     :: "l"(&S->arrive[w64]), "l"(bit) : "memory");

        // ---- precompute everything dest-independent while siblings arrive ----
        float gy1 = gb.x, gx1 = gb.y, gy2 = gb.z, gx2 = gb.w;
        float4 dl = make_float4(0.f, 0.f, 0.f, 0.f);
        float rk = 0.0f;
        if (pos) {
            const float h  = pr.z - pr.x, wd = pr.w - pr.y;
            const float cy = pr.x + 0.5f * h, cx = pr.y + 0.5f * wd;
            const float gh = gy2 - gy1, gw = gx2 - gx1;
            const float gcy = gy1 + 0.5f * gh, gcx = gx1 + 0.5f * gw;
            dl.x = ((gcy - cy) / h)  / 0.1f;
            dl.y = ((gcx - cx) / wd) / 0.1f;
            dl.z = logf(gh / h)  / 0.2f;
            dl.w = logf(gw / wd) / 0.2f;
            rk = (float)gt_ranks[b * NG + bj];
        } else {
            gy1 = gx1 = gy2 = gx2 = 0.0f;    // roi_gt = 0 for negatives
        }
        // integer spatial box (window transform + denorm + round-half-even)
        int4 box;
        {
            const float win0 = 128.0f / 1023.0f;
            const float win2 = 895.0f / 1023.0f;
            const float wsc  = win2 - win0;
            int by1 = (int)rintf(((gy1 - win0) / wsc) * 479.0f);
            int bx1 = (int)rintf(gx1 * 639.0f);
            int by2 = (int)rintf(((gy2 - win0) / wsc) * 479.0f + 1.0f);
            int bx2 = (int)rintf(gx2 * 639.0f + 1.0f);
            if (!((by2 - by1) * (bx2 - bx1) > 0)) { by1 = bx1 = by2 = bx2 = 0; }
            box = make_int4(by1, bx1, by2, bx2);
        }

        // ---- wait for all 128 arrivals of this image ----
        unsigned long long a0, a1;
        int spins = 0;
        for (;;) {
            asm volatile("ld.acquire.gpu.global.b64 %0, [%1];"
                         : "=l"(a0) : "l"(&S->arrive[0]) : "memory");
            asm volatile("ld.acquire.gpu.global.b64 %0, [%1];"
                         : "=l"(a1) : "l"(&S->arrive[1]) : "memory");
            if ((a0 & a1) == ~0ULL) break;
            if (++spins > 128) __nanosleep(32);
        }
        // pos words: L1-bypassing relaxed loads, ordered after the acquires
        unsigned long long p0, p1;
        asm volatile("ld.relaxed.gpu.global.b64 %0, [%1];"
                     : "=l"(p0) : "l"(&S->pos[0]) : "memory");
        asm volatile("ld.relaxed.gpu.global.b64 %0, [%1];"
                     : "=l"(p1) : "l"(&S->pos[1]) : "memory");

        const int npos  = __popcll(p0) + __popcll(p1);
        const unsigned long long myw = (p < 64) ? p0 : p1;
        int below = __popcll(myw & (bit - 1));
        if (p >= 64) below += __popcll(p0);
        const int dest = pos ? below : (npos + (p - below));
        const int dbo  = (b << 7) + dest;

        // ---- done counter; the 128th arriver resets this image's sync ----
        int old;
        {
            int one = 1;
            asm volatile("atom.release.gpu.global.add.s32 %0, [%1], %2;"
                         : "=r"(old) : "l"(&S->done), "r"(one) : "memory");
        }
        if (old == NK - 1) {
            const unsigned long long z = 0ULL;
            asm volatile("st.relaxed.gpu.global.b64 [%0], %1;" :: "l"(&S->arrive[0]), "l"(z) : "memory");
            asm volatile("st.relaxed.gpu.global.b64 [%0], %1;" :: "l"(&S->arrive[1]), "l"(z) : "memory");
            asm volatile("st.relaxed.gpu.global.b64 [%0], %1;" :: "l"(&S->pos[0]),    "l"(z) : "memory");
            asm volatile("st.relaxed.gpu.global.b64 [%0], %1;" :: "l"(&S->pos[1]),    "l"(z) : "memory");
            int zi = 0;
            asm volatile("st.relaxed.gpu.global.b32 [%0], %1;" :: "l"(&S->done), "r"(zi) : "memory");
        }

        // ---- scalar outputs for this ROI ----
        ((float4*)(out + OFF_ROIS))[dbo]   = pr;
        ((float4*)(out + OFF_DELTAS))[dbo] = dl;
        out[OFF_RANKS + dbo] = rk;

        s_dest = dest;
        s_box  = box;
    }
    __syncthreads();

    // ---- scatter: payload + analytic spatial to dest slot ----
    const int dest = s_dest;
    const int4 bx  = s_box;
    const int dbo  = (b << 7) + dest;

    ((float4*)(out + OFF_OBJ))[(size_t)dbo * 256 + t] = payload;

    // analytic spatial: thread t writes float4 covering elements [4t, 4t+4)
    const int row  = t >> 3;
    const int col0 = (t & 7) * 4;
    float4 v = make_float4(0.f, 0.f, 0.f, 0.f);
    if (row >= 4 && row < 28) {
        const int r1 = 20 * (row - 4) + 9;
        const float fy = (float)((bx.x < r1)     && (r1     < bx.z))
                       + (float)((bx.x < r1 + 1) && (r1 + 1 < bx.z));
        const float sc = 0.25f * fy;
        float* vv = &v.x;
        #pragma unroll
        for (int k = 0; k < 4; k++) {
            const int c1 = 20 * (col0 + k) + 9;
            const float fx = (float)((bx.y < c1)     && (c1     < bx.w))
                           + (float)((bx.y < c1 + 1) && (c1 + 1 < bx.w));
            vv[k] = sc * fx;
        }
    }
    ((float4*)(out + OFF_SPATIAL))[(size_t)dbo * 256 + t] = v;
}

extern "C" void kernel_launch(void* const* d_in, const int* in_sizes, int n_in,
                              void* d_out, int out_size)
{
    const float* proposals = (const float*)d_in[0];
    const float* obj_feat  = (const float*)d_in[1];
    const float* gt_boxes  = (const float*)d_in[2];
    const int*   gt_ranks  = (const int*)  d_in[3];
    float* out = (float*)d_out;

    fused_kernel<<<NB * NK, 256>>>(proposals, obj_feat, gt_boxes, gt_ranks, out);
}

// round 13
// speedup vs baseline: 1.1913x; 1.0144x over previous
#include <cuda_runtime.h>

#define NB 4
#define NK 128
#define NG 128

// ---- output layout (float32, tuple flattened & concatenated) ----
#define OFF_ROIS    0
#define OFF_OBJ     2048
#define OFF_DELTAS  526336
#define OFF_RANKS   528384
#define OFF_SPATIAL 528896

// Per-image sync state, one 128B line each (zero-initialized; the 128th
// done-arriver of each image resets it for the next launch).
struct __align__(128) ImgSync {
    unsigned long long arrive[2];   // 128 arrival bits
    unsigned long long pos[2];      // 128 positive bits
    int done;
    int pad[23];
};
__device__ ImgSync g_sync[NB];

// grid = 256, block = 256. Block g owns source proposals sA=2g, sB=2g+1 of
// image b = sA>>7. Warps 0-3 compute A's 128 IoUs (1/thread), warps 4-7 B's.
// Leaders t=0 (A) and t=128 (B) publish bits, spin for the image's 128
// arrivals, derive dest locally, write scalar outputs. Then all 256 threads
// scatter both payloads + analytic spatial maps.
__global__ void __launch_bounds__(256) fused_kernel(
    const float* __restrict__ proposals,
    const float* __restrict__ obj_feat,
    const float* __restrict__ gt_boxes,
    const int*   __restrict__ gt_ranks,
    float*       __restrict__ out)
{
    const int g  = blockIdx.x;
    const int sA = g * 2;            // source index b*128 + p
    const int sB = sA + 1;
    const int b  = sA >> 7;
    const int t  = threadIdx.x;
    const int side = t >> 7;         // 0 = proposal A, 1 = proposal B
    const int lt   = t & 127;        // lane within side

    // ---- payload loads first: 2 independent streams, overlap everything ----
    const float4 payA = ((const float4*)obj_feat)[(size_t)sA * 256 + t];
    const float4 payB = ((const float4*)obj_feat)[(size_t)sB * 256 + t];

    __shared__ float s_bi[8], s_bu[8];
    __shared__ int   s_bj[8];
    __shared__ int   s_dest[2];
    __shared__ int4  s_box[2];

    // ---- per-thread IoU: lane lt handles GT index lt for its side ----
    {
        const int s = side ? sB : sA;
        const float4 pr = ((const float4*)proposals)[s];            // broadcast
        const float4 gt = ((const float4*)gt_boxes)[(b << 7) + lt];
        const float ap = (pr.z - pr.x) * (pr.w - pr.y);
        const float dy = fminf(pr.z, gt.z) - fmaxf(pr.x, gt.x);
        const float dx = fminf(pr.w, gt.w) - fmaxf(pr.y, gt.y);
        float bi = fmaxf(dx, 0.0f) * fmaxf(dy, 0.0f);               // inter
        float bu = ap + (gt.z - gt.x) * (gt.w - gt.y) - bi;         // union
        int   bj = lt;
        // warp argmax; shfl_down partner has HIGHER gt index, so strict >
        // keeps the first (lowest-index) max — matches jnp.argmax.
        #pragma unroll
        for (int off = 16; off; off >>= 1) {
            const float oi = __shfl_down_sync(0xFFFFFFFFu, bi, off);
            const float ou = __shfl_down_sync(0xFFFFFFFFu, bu, off);
            const int   oj = __shfl_down_sync(0xFFFFFFFFu, bj, off);
            if (oi * bu > bi * ou) { bi = oi; bu = ou; bj = oj; }
        }
        if ((t & 31) == 0) { s_bi[t >> 5] = bi; s_bu[t >> 5] = bu; s_bj[t >> 5] = bj; }
    }
    __syncthreads();

    // ---- leaders: t=0 handles A, t=128 handles B ----
    if (lt == 0) {
        const int p = (side ? sB : sA) & 127;
        const int w0 = side * 4;
        // merge this side's 4 warp winners in ascending-index order
        float bi = s_bi[w0], bu = s_bu[w0];
        int   bj = s_bj[w0];
        #pragma unroll
        for (int w = 1; w < 4; w++)
            if (s_bi[w0 + w] * bu > bi * s_bu[w0 + w]) {
                bi = s_bi[w0 + w]; bu = s_bu[w0 + w]; bj = s_bj[w0 + w];
            }

        const float4 pr = ((const float4*)proposals)[(b << 7) + p];
        const float4 gb = ((const float4*)gt_boxes)[(b << 7) + bj];

        // exact IoU for the winner (bit-matches reference threshold test)
        const float ap = (pr.z - pr.x) * (pr.w - pr.y);
        const float iy1 = fmaxf(pr.x, gb.x);
        const float ix1 = fmaxf(pr.y, gb.y);
        const float iy2 = fminf(pr.z, gb.z);
        const float ix2 = fminf(pr.w, gb.w);
        const float inter = fmaxf(ix2 - ix1, 0.0f) * fmaxf(iy2 - iy1, 0.0f);
        const float ag = (gb.z - gb.x) * (gb.w - gb.y);
        const float iou = inter / (ap + ag - inter);
        const int pos = (iou >= 0.5f) ? 1 : 0;

        // ---- publish this proposal's bits (RED: no-return) ----
        ImgSync* S = &g_sync[b];
        const unsigned long long bit = 1ULL << (p & 63);
        const int w64 = p >> 6;
        if (pos)
            asm volatile("red.relaxed.gpu.global.or.b64 [%0], %1;"
                         :: "l"(&S->pos[w64]), "l"(bit) : "memory");
        asm volatile("red.release.gpu.global.or.b64 [%0], %1;"
                     :: "l"(&S->arrive[w64]), "l"(bit) : "memory");

        // ---- dest-independent precompute while siblings arrive ----
        float gy1 = gb.x, gx1 = gb.y, gy2 = gb.z, gx2 = gb.w;
        float4 dl = make_float4(0.f, 0.f, 0.f, 0.f);
        float rk = 0.0f;
        if (pos) {
            const float h  = pr.z - pr.x, wd = pr.w - pr.y;
            const float cy = pr.x + 0.5f * h, cx = pr.y + 0.5f * wd;
            const float gh = gy2 - gy1, gw = gx2 - gx1;
            const float gcy = gy1 + 0.5f * gh, gcx = gx1 + 0.5f * gw;
            dl.x = ((gcy - cy) / h)  / 0.1f;
            dl.y = ((gcx - cx) / wd) / 0.1f;
            dl.z = logf(gh / h)  / 0.2f;
            dl.w = logf(gw / wd) / 0.2f;
            rk = (float)gt_ranks[b * NG + bj];
        } else {
            gy1 = gx1 = gy2 = gx2 = 0.0f;    // roi_gt = 0 for negatives
        }
        int4 box;
        {
            // integer spatial box (window transform + denorm + round-half-even)
            const float win0 = 128.0f / 1023.0f;
            const float win2 = 895.0f / 1023.0f;
            const float wsc  = win2 - win0;
            int by1 = (int)rintf(((gy1 - win0) / wsc) * 479.0f);
            int bx1 = (int)rintf(gx1 * 639.0f);
            int by2 = (int)rintf(((gy2 - win0) / wsc) * 479.0f + 1.0f);
            int bx2 = (int)rintf(gx2 * 639.0f + 1.0f);
            if (!((by2 - by1) * (bx2 - bx1) > 0)) { by1 = bx1 = by2 = bx2 = 0; }
            box = make_int4(by1, bx1, by2, bx2);
        }

        // ---- wait for all 128 arrivals of this image ----
        unsigned long long a0, a1;
        int spins = 0;
        for (;;) {
            asm volatile("ld.acquire.gpu.global.b64 %0, [%1];"
                         : "=l"(a0) : "l"(&S->arrive[0]) : "memory");
            asm volatile("ld.acquire.gpu.global.b64 %0, [%1];"
                         : "=l"(a1) : "l"(&S->arrive[1]) : "memory");
            if ((a0 & a1) == ~0ULL) break;
            if (++spins > 128) __nanosleep(32);
        }
        unsigned long long p0, p1;
        asm volatile("ld.relaxed.gpu.global.b64 %0, [%1];"
                     : "=l"(p0) : "l"(&S->pos[0]) : "memory");
        asm volatile("ld.relaxed.gpu.global.b64 %0, [%1];"
                     : "=l"(p1) : "l"(&S->pos[1]) : "memory");

        const int npos  = __popcll(p0) + __popcll(p1);
        const unsigned long long myw = (p < 64) ? p0 : p1;
        int below = __popcll(myw & (bit - 1));
        if (p >= 64) below += __popcll(p0);
        const int dest = pos ? below : (npos + (p - below));
        const int dbo  = (b << 7) + dest;

        // ---- done counter; the 128th arriver resets this image's sync ----
        int old;
        {
            int one = 1;
            asm volatile("atom.release.gpu.global.add.s32 %0, [%1], %2;"
                         : "=r"(old) : "l"(&S->done), "r"(one) : "memory");
        }
        if (old == NK - 1) {
            const unsigned long long z = 0ULL;
            asm volatile("st.relaxed.gpu.global.b64 [%0], %1;" :: "l"(&S->arrive[0]), "l"(z) : "memory");
            asm volatile("st.relaxed.gpu.global.b64 [%0], %1;" :: "l"(&S->arrive[1]), "l"(z) : "memory");
            asm volatile("st.relaxed.gpu.global.b64 [%0], %1;" :: "l"(&S->pos[0]),    "l"(z) : "memory");
            asm volatile("st.relaxed.gpu.global.b64 [%0], %1;" :: "l"(&S->pos[1]),    "l"(z) : "memory");
            int zi = 0;
            asm volatile("st.relaxed.gpu.global.b32 [%0], %1;" :: "l"(&S->done), "r"(zi) : "memory");
        }

        // ---- scalar outputs for this ROI ----
        ((float4*)(out + OFF_ROIS))[dbo]   = pr;
        ((float4*)(out + OFF_DELTAS))[dbo] = dl;
        out[OFF_RANKS + dbo] = rk;

        s_dest[side] = dest;
        s_box[side]  = box;
    }
    __syncthreads();

    // ---- scatter: both payloads + analytic spatial maps ----
    const int dboA = (b << 7) + s_dest[0];
    const int dboB = (b << 7) + s_dest[1];
    const int4 bxA = s_box[0];
    const int4 bxB = s_box[1];

    ((float4*)(out + OFF_OBJ))[(size_t)dboA * 256 + t] = payA;
    ((float4*)(out + OFF_OBJ))[(size_t)dboB * 256 + t] = payB;

    // analytic spatial: thread t writes float4 covering elements [4t, 4t+4)
    const int row  = t >> 3;
    const int col0 = (t & 7) * 4;
    float4 vA = make_float4(0.f, 0.f, 0.f, 0.f);
    float4 vB = make_float4(0.f, 0.f, 0.f, 0.f);
    if (row >= 4 && row < 28) {
        const int r1 = 20 * (row - 4) + 9;
        const float fyA = (float)((bxA.x < r1)     && (r1     < bxA.z))
                        + (float)((bxA.x < r1 + 1) && (r1 + 1 < bxA.z));
        const float fyB = (float)((bxB.x < r1)     && (r1     < bxB.z))
                        + (float)((bxB.x < r1 + 1) && (r1 + 1 < bxB.z));
        const float scA = 0.25f * fyA;
        const float scB = 0.25f * fyB;
        float* pA = &vA.x;
        float* pB = &vB.x;
        #pragma unroll
        for (int k = 0; k < 4; k++) {
            const int c1 = 20 * (col0 + k) + 9;
            const float fxA = (float)((bxA.y < c1)     && (c1     < bxA.w))
                            + (float)((bxA.y < c1 + 1) && (c1 + 1 < bxA.w));
            const float fxB = (float)((bxB.y < c1)     && (c1     < bxB.w))
                            + (float)((bxB.y < c1 + 1) && (c1 + 1 < bxB.w));
            pA[k] = scA * fxA;
            pB[k] = scB * fxB;
        }
    }
    ((float4*)(out + OFF_SPATIAL))[(size_t)dboA * 256 + t] = vA;
    ((float4*)(out + OFF_SPATIAL))[(size_t)dboB * 256 + t] = vB;
}

extern "C" void kernel_launch(void* const* d_in, const int* in_sizes, int n_in,
                              void* d_out, int out_size)
{
    const float* proposals = (const float*)d_in[0];
    const float* obj_feat  = (const float*)d_in[1];
    const float* gt_boxes  = (const float*)d_in[2];
    const int*   gt_ranks  = (const int*)  d_in[3];
    float* out = (float*)d_out;

    fused_kernel<<<256, 256>>>(proposals, obj_feat, gt_boxes, gt_ranks, out);
}